// round 3
// baseline (speedup 1.0000x reference)
#include <cuda_runtime.h>

// VQ-VAE VectorQuantizer — bit-faithful to the jax fp32 reference:
//   d_k = fl( fl(sx + se_k) - fl(2 * P_k) ),  argmin_k (first min)
// sx = |x_row|^2 (any fp32 in the right binade works: grid-shift invariance),
// se_k = |e_k|^2, P_k = x.e_k accumulated as a sequential fp32 FMA chain
// over c = 0..63 (matches Eigen/XLA sequential depth loop).
//
// x: [32, 64(C), 64, 64] NCHW float32  (d_in[0])
// codebook: [1024, 64] float32         (d_in[1])
// out f32: [ loss(1) | quantized NCHW (8388608) | idx (131072) ]

#define TPB 128
#define RPB 256
#define RSTRIDE 68
#define DIM 64
#define KCODES 1024
#define NROWS (32 * 64 * 64)
#define NBLOCKS (NROWS / RPB)
#define QELEMS (NROWS * DIM)
#define KCH 64

__device__ float g_se[KCODES];         // sum(e_k^2)
__device__ float g_losspart[NBLOCKS];

// ---------------------------------------------------------------------------
__global__ void vq_prep(const float* __restrict__ cb) {
    int k = blockIdx.x * blockDim.x + threadIdx.x;
    if (k < KCODES) {
        const float4* r = reinterpret_cast<const float4*>(cb + k * DIM);
        float s = 0.f;
#pragma unroll
        for (int i = 0; i < DIM / 4; ++i) {
            float4 v = r[i];
            s = fmaf(v.x, v.x, s);
            s = fmaf(v.y, v.y, s);
            s = fmaf(v.z, v.z, s);
            s = fmaf(v.w, v.w, s);
        }
        g_se[k] = s;
    }
}

// ---------------------------------------------------------------------------
__global__ __launch_bounds__(TPB, 2) void vq_main(const float* __restrict__ x,
                                                  const float* __restrict__ cb,
                                                  float* __restrict__ out) {
    extern __shared__ float smem[];
    float* xs  = smem;                       // [RPB][RSTRIDE]
    float* es  = smem + RPB * RSTRIDE;       // [KCH][DIM]
    float* red = es + KCH * DIM;             // [TPB]

    const int tid = threadIdx.x;
    const int n0  = blockIdx.x * RPB;
    const int b   = n0 >> 12;
    const int off = n0 & 4095;
    const float* xb = x + b * (DIM * 4096) + off;

    // Load x tile: coalesced float4 over rows, strided smem store.
    for (int i = tid; i < DIM * (RPB / 4); i += TPB) {
        int c  = i >> 6;
        int r4 = (i & 63) << 2;
        float4 v = *reinterpret_cast<const float4*>(xb + c * 4096 + r4);
        xs[(r4 + 0) * RSTRIDE + c] = v.x;
        xs[(r4 + 1) * RSTRIDE + c] = v.y;
        xs[(r4 + 2) * RSTRIDE + c] = v.z;
        xs[(r4 + 3) * RSTRIDE + c] = v.w;
    }
    __syncthreads();

    // Per-row |x|^2 (any fp32 summation order is fine — binade is all that matters).
    float sx0 = 0.f, sx1 = 0.f;
#pragma unroll
    for (int c4 = 0; c4 < DIM / 4; ++c4) {
        float4 a = *reinterpret_cast<const float4*>(&xs[tid * RSTRIDE + c4 * 4]);
        float4 v = *reinterpret_cast<const float4*>(&xs[(tid + TPB) * RSTRIDE + c4 * 4]);
        sx0 = fmaf(a.x, a.x, sx0); sx0 = fmaf(a.y, a.y, sx0);
        sx0 = fmaf(a.z, a.z, sx0); sx0 = fmaf(a.w, a.w, sx0);
        sx1 = fmaf(v.x, v.x, sx1); sx1 = fmaf(v.y, v.y, sx1);
        sx1 = fmaf(v.z, v.z, sx1); sx1 = fmaf(v.w, v.w, sx1);
    }

    float best0 = 3.0e38f, best1 = 3.0e38f;
    int   bidx0 = 0,       bidx1 = 0;

    for (int kc = 0; kc < KCODES / KCH; ++kc) {
        __syncthreads();
        const float4* cb4 = reinterpret_cast<const float4*>(cb + kc * KCH * DIM);
        for (int i = tid; i < KCH * DIM / 4; i += TPB)
            reinterpret_cast<float4*>(es)[i] = cb4[i];
        __syncthreads();

        for (int kg = 0; kg < KCH; kg += 8) {
            float acc0[8], acc1[8];
#pragma unroll
            for (int k = 0; k < 8; ++k) { acc0[k] = 0.f; acc1[k] = 0.f; }

            // Sequential-in-c FMA chain per accumulator (bitwise = sequential
            // depth loop of the reference GEMM).
#pragma unroll 4
            for (int c4 = 0; c4 < DIM / 4; ++c4) {
                float4 xa = *reinterpret_cast<const float4*>(&xs[tid * RSTRIDE + c4 * 4]);
                float4 xv = *reinterpret_cast<const float4*>(&xs[(tid + TPB) * RSTRIDE + c4 * 4]);
#pragma unroll
                for (int k = 0; k < 8; ++k) {
                    float4 e = *reinterpret_cast<const float4*>(&es[(kg + k) * DIM + c4 * 4]);
                    acc0[k] = fmaf(xa.x, e.x, acc0[k]);
                    acc0[k] = fmaf(xa.y, e.y, acc0[k]);
                    acc0[k] = fmaf(xa.z, e.z, acc0[k]);
                    acc0[k] = fmaf(xa.w, e.w, acc0[k]);
                    acc1[k] = fmaf(xv.x, e.x, acc1[k]);
                    acc1[k] = fmaf(xv.y, e.y, acc1[k]);
                    acc1[k] = fmaf(xv.z, e.z, acc1[k]);
                    acc1[k] = fmaf(xv.w, e.w, acc1[k]);
                }
            }
#pragma unroll
            for (int k = 0; k < 8; ++k) {
                int kk = kc * KCH + kg + k;
                float se = g_se[kk];
                // Exactly the reference's association and roundings:
                // A = fl(sx + se); d = fl(A - fl(2*P))   (2*P exact)
                float A0 = __fadd_rn(sx0, se);
                float A1 = __fadd_rn(sx1, se);
                float d0 = __fadd_rn(A0, __fmul_rn(-2.0f, acc0[k]));
                float d1 = __fadd_rn(A1, __fmul_rn(-2.0f, acc1[k]));
                // strict < , ascending k  ==  jnp.argmin first-min rule
                if (d0 < best0) { best0 = d0; bidx0 = kk; }
                if (d1 < best1) { best1 = d1; bidx1 = kk; }
            }
        }
    }

    // Epilogue: gather, write quantized (NCHW, coalesced per c), idx, loss.
    float lsum = 0.f;
    float* qout = out + 1;
    float* iout = out + 1 + QELEMS;
#pragma unroll 1
    for (int r = 0; r < 2; ++r) {
        int row  = tid + r * TPB;
        int code = r ? bidx1 : bidx0;
        const float* e = cb + code * DIM;
        float* q = qout + b * (DIM * 4096) + off + row;
#pragma unroll
        for (int c = 0; c < DIM; ++c) {
            float ec = __ldg(e + c);
            float d  = ec - xs[row * RSTRIDE + c];
            lsum = fmaf(d, d, lsum);
            q[c * 4096] = ec;
        }
        iout[n0 + row] = (float)code;
    }

    red[tid] = lsum;
    __syncthreads();
#pragma unroll
    for (int s = TPB / 2; s > 0; s >>= 1) {
        if (tid < s) red[tid] += red[tid + s];
        __syncthreads();
    }
    if (tid == 0) g_losspart[blockIdx.x] = red[0];
}

// ---------------------------------------------------------------------------
__global__ void vq_finalize(float* __restrict__ out) {
    __shared__ float red[NBLOCKS];
    int tid = threadIdx.x;
    red[tid] = g_losspart[tid];
    __syncthreads();
    for (int s = NBLOCKS / 2; s > 0; s >>= 1) {
        if (tid < s) red[tid] += red[tid + s];
        __syncthreads();
    }
    if (tid == 0) out[0] = red[0] * (1.25f / (float)QELEMS);
}

// ---------------------------------------------------------------------------
extern "C" void kernel_launch(void* const* d_in, const int* in_sizes, int n_in,
                              void* d_out, int out_size) {
    const float* x  = (const float*)d_in[0];
    const float* cb = (const float*)d_in[1];
    float* out = (float*)d_out;

    const size_t smem = (size_t)(RPB * RSTRIDE + KCH * DIM + TPB) * sizeof(float);
    cudaFuncSetAttribute(vq_main, cudaFuncAttributeMaxDynamicSharedMemorySize, (int)smem);

    vq_prep<<<KCODES / 256, 256>>>(cb);
    vq_main<<<NBLOCKS, TPB, smem>>>(x, cb, out);
    vq_finalize<<<1, NBLOCKS>>>(out);
}

// round 4
// speedup vs baseline: 1.2122x; 1.2122x over previous
#include <cuda_runtime.h>
#include <cstdint>

// VQ-VAE VectorQuantizer — bit-faithful argmin (see R2), mainloop via packed
// fma.rn.f32x2 (2 codes per instruction, per-lane IEEE fp32 => same bits).
// out f32: [ loss(1) | quantized NCHW (8388608) | idx (131072) ]

#define TPB 128
#define RPB 256
#define RSTRIDE 68
#define DIM 64
#define KCODES 1024
#define NROWS (32 * 64 * 64)
#define NBLOCKS (NROWS / RPB)
#define QELEMS (NROWS * DIM)
#define KCH 64

__device__ float g_se[KCODES];
__device__ float g_losspart[NBLOCKS];

typedef unsigned long long u64;

__device__ __forceinline__ void fma2(u64& acc, u64 a, u64 b) {
    asm("fma.rn.f32x2 %0, %1, %2, %3;" : "=l"(acc) : "l"(a), "l"(b), "l"(acc));
}
__device__ __forceinline__ u64 bcast2(float x) {
    u64 d; unsigned r = __float_as_uint(x);
    asm("mov.b64 %0, {%1,%1};" : "=l"(d) : "r"(r));
    return d;
}
__device__ __forceinline__ void unpack2(u64 v, float& lo, float& hi) {
    unsigned a, b;
    asm("mov.b64 {%0,%1}, %2;" : "=r"(a), "=r"(b) : "l"(v));
    lo = __uint_as_float(a); hi = __uint_as_float(b);
}

__global__ void vq_prep(const float* __restrict__ cb) {
    int k = blockIdx.x * blockDim.x + threadIdx.x;
    if (k < KCODES) {
        const float4* r = reinterpret_cast<const float4*>(cb + k * DIM);
        float s = 0.f;
#pragma unroll
        for (int i = 0; i < DIM / 4; ++i) {
            float4 v = r[i];
            s = fmaf(v.x, v.x, s); s = fmaf(v.y, v.y, s);
            s = fmaf(v.z, v.z, s); s = fmaf(v.w, v.w, s);
        }
        g_se[k] = s;
    }
}

__global__ __launch_bounds__(TPB, 2) void vq_main(const float* __restrict__ x,
                                                  const float* __restrict__ cb,
                                                  float* __restrict__ out) {
    extern __shared__ float smem[];
    float* xs  = smem;                        // [RPB][RSTRIDE]
    float* es2 = smem + RPB * RSTRIDE;        // 32 pairs x 64 ch x float2 (16KB)
    float* red = es2 + KCH * DIM;             // [TPB]

    const int tid = threadIdx.x;
    const int n0  = blockIdx.x * RPB;
    const int b   = n0 >> 12;
    const int off = n0 & 4095;
    const float* xb = x + b * (DIM * 4096) + off;

    for (int i = tid; i < DIM * (RPB / 4); i += TPB) {
        int c  = i >> 6;
        int r4 = (i & 63) << 2;
        float4 v = *reinterpret_cast<const float4*>(xb + c * 4096 + r4);
        xs[(r4 + 0) * RSTRIDE + c] = v.x;
        xs[(r4 + 1) * RSTRIDE + c] = v.y;
        xs[(r4 + 2) * RSTRIDE + c] = v.z;
        xs[(r4 + 3) * RSTRIDE + c] = v.w;
    }
    __syncthreads();

    float sx0 = 0.f, sx1 = 0.f;
#pragma unroll
    for (int c4 = 0; c4 < DIM / 4; ++c4) {
        float4 a = *reinterpret_cast<const float4*>(&xs[tid * RSTRIDE + c4 * 4]);
        float4 v = *reinterpret_cast<const float4*>(&xs[(tid + TPB) * RSTRIDE + c4 * 4]);
        sx0 = fmaf(a.x, a.x, sx0); sx0 = fmaf(a.y, a.y, sx0);
        sx0 = fmaf(a.z, a.z, sx0); sx0 = fmaf(a.w, a.w, sx0);
        sx1 = fmaf(v.x, v.x, sx1); sx1 = fmaf(v.y, v.y, sx1);
        sx1 = fmaf(v.z, v.z, sx1); sx1 = fmaf(v.w, v.w, sx1);
    }

    float best0 = 3.0e38f, best1 = 3.0e38f;
    int   bidx0 = 0,       bidx1 = 0;

    for (int kc = 0; kc < KCODES / KCH; ++kc) {
        __syncthreads();
        // Load 64-code chunk pair-interleaved: es2[p*128 + c*2 + (k&1)] = e_k[c]
        const float4* cb4 = reinterpret_cast<const float4*>(cb + kc * KCH * DIM);
        for (int i = tid; i < KCH * DIM / 4; i += TPB) {
            int k  = i >> 4;
            int c0 = (i & 15) << 2;
            float4 v = cb4[i];
            float* dst = es2 + (k >> 1) * 128 + (k & 1) + c0 * 2;
            dst[0] = v.x; dst[2] = v.y; dst[4] = v.z; dst[6] = v.w;
        }
        __syncthreads();

        for (int kg = 0; kg < KCH; kg += 16) {       // 8 code-pairs per iter
            u64 acc0[8], acc1[8];
#pragma unroll
            for (int p = 0; p < 8; ++p) { acc0[p] = 0ull; acc1[p] = 0ull; }

#pragma unroll 4
            for (int c4 = 0; c4 < DIM / 4; ++c4) {
                float4 xa = *reinterpret_cast<const float4*>(&xs[tid * RSTRIDE + c4 * 4]);
                float4 xv = *reinterpret_cast<const float4*>(&xs[(tid + TPB) * RSTRIDE + c4 * 4]);
                u64 a0[4], a1[4];
                a0[0] = bcast2(xa.x); a0[1] = bcast2(xa.y);
                a0[2] = bcast2(xa.z); a0[3] = bcast2(xa.w);
                a1[0] = bcast2(xv.x); a1[1] = bcast2(xv.y);
                a1[2] = bcast2(xv.z); a1[3] = bcast2(xv.w);
#pragma unroll
                for (int p = 0; p < 8; ++p) {
                    const u64* ep = reinterpret_cast<const u64*>(
                        es2 + ((kg >> 1) + p) * 128 + c4 * 8);
                    ulonglong2 eA = *reinterpret_cast<const ulonglong2*>(ep);
                    ulonglong2 eB = *reinterpret_cast<const ulonglong2*>(ep + 2);
                    fma2(acc0[p], a0[0], eA.x); fma2(acc0[p], a0[1], eA.y);
                    fma2(acc0[p], a0[2], eB.x); fma2(acc0[p], a0[3], eB.y);
                    fma2(acc1[p], a1[0], eA.x); fma2(acc1[p], a1[1], eA.y);
                    fma2(acc1[p], a1[2], eB.x); fma2(acc1[p], a1[3], eB.y);
                }
            }
#pragma unroll
            for (int p = 0; p < 8; ++p) {
                int ke = kc * KCH + kg + 2 * p;       // even code, then odd
                float Pe, Po;
                unpack2(acc0[p], Pe, Po);
                float de = __fadd_rn(__fadd_rn(sx0, g_se[ke]),     __fmul_rn(-2.0f, Pe));
                float dd = __fadd_rn(__fadd_rn(sx0, g_se[ke + 1]), __fmul_rn(-2.0f, Po));
                if (de < best0) { best0 = de; bidx0 = ke; }
                if (dd < best0) { best0 = dd; bidx0 = ke + 1; }
                unpack2(acc1[p], Pe, Po);
                de = __fadd_rn(__fadd_rn(sx1, g_se[ke]),     __fmul_rn(-2.0f, Pe));
                dd = __fadd_rn(__fadd_rn(sx1, g_se[ke + 1]), __fmul_rn(-2.0f, Po));
                if (de < best1) { best1 = de; bidx1 = ke; }
                if (dd < best1) { best1 = dd; bidx1 = ke + 1; }
            }
        }
    }

    // Epilogue: gather, write quantized (NCHW, coalesced per c), idx, loss.
    float lsum = 0.f;
    float* qout = out + 1;
    float* iout = out + 1 + QELEMS;
#pragma unroll 1
    for (int r = 0; r < 2; ++r) {
        int row  = tid + r * TPB;
        int code = r ? bidx1 : bidx0;
        const float* e = cb + code * DIM;
        float* q = qout + b * (DIM * 4096) + off + row;
#pragma unroll
        for (int c = 0; c < DIM; ++c) {
            float ec = __ldg(e + c);
            float d  = ec - xs[row * RSTRIDE + c];
            lsum = fmaf(d, d, lsum);
            q[c * 4096] = ec;
        }
        iout[n0 + row] = (float)code;
    }

    red[tid] = lsum;
    __syncthreads();
#pragma unroll
    for (int s = TPB / 2; s > 0; s >>= 1) {
        if (tid < s) red[tid] += red[tid + s];
        __syncthreads();
    }
    if (tid == 0) g_losspart[blockIdx.x] = red[0];
}

__global__ void vq_finalize(float* __restrict__ out) {
    __shared__ float red[NBLOCKS];
    int tid = threadIdx.x;
    red[tid] = g_losspart[tid];
    __syncthreads();
    for (int s = NBLOCKS / 2; s > 0; s >>= 1) {
        if (tid < s) red[tid] += red[tid + s];
        __syncthreads();
    }
    if (tid == 0) out[0] = red[0] * (1.25f / (float)QELEMS);
}

extern "C" void kernel_launch(void* const* d_in, const int* in_sizes, int n_in,
                              void* d_out, int out_size) {
    const float* x  = (const float*)d_in[0];
    const float* cb = (const float*)d_in[1];
    float* out = (float*)d_out;

    const size_t smem = (size_t)(RPB * RSTRIDE + KCH * DIM + TPB) * sizeof(float);
    cudaFuncSetAttribute(vq_main, cudaFuncAttributeMaxDynamicSharedMemorySize, (int)smem);

    vq_prep<<<KCODES / 256, 256>>>(cb);
    vq_main<<<NBLOCKS, TPB, smem>>>(x, cb, out);
    vq_finalize<<<1, NBLOCKS>>>(out);
}